// round 4
// baseline (speedup 1.0000x reference)
#include <cuda_runtime.h>
#include <cuda_bf16.h>
#include <math.h>

// Problem shape (fixed by dataset): T=512, N=512, C=80, S=128
#define TT 512
#define CC 80
#define SS 128
#define LL 257             // 2*S + 1 lattice cells (0..256)
#define NEGV (-1e30f)
#define NTHREADS 256       // 8 full warps; thread t handles cell t+1, thread 0 also cell 0
#define LOG2E 1.4426950408889634f
#define LN2   0.6931471805599453f

__device__ __forceinline__ float ex2f(float x) {
    float r; asm("ex2.approx.ftz.f32 %0, %1;" : "=f"(r) : "f"(x)); return r;
}
__device__ __forceinline__ float lg2f(float x) {
    float r; asm("lg2.approx.f32 %0, %1;" : "=f"(r) : "f"(x)); return r;
}

__global__ __launch_bounds__(NTHREADS)
void ctc_loss_kernel(const float* __restrict__ log_probs,     // (T, N, C)
                     const int*   __restrict__ targets,       // (N, S)
                     const int*   __restrict__ input_lengths, // (N,)
                     const int*   __restrict__ target_lengths,// (N,)
                     float*       __restrict__ out,           // (N,)
                     int N)
{
    // cells 0..256 live at indices 2..258; indices 0,1 are a permanent NEG pad
    __shared__ float shA[2][LL + 2];

    const int tid = threadIdx.x;
    const int s   = tid + 1;              // my main lattice cell (1..256)
    const int n   = blockIdx.x;
    const int len = input_lengths[n];

    // Time-invariant per-cell state: label class + skip permission (registers)
    int  myc  = 0;
    bool skip = false;
    if (s & 1) {                          // odd cells carry labels
        int j = s >> 1;
        myc = targets[n * SS + j];
        if (s >= 3) skip = (myc != targets[n * SS + j - 1]);
    }

    const size_t tstride = (size_t)N * CC;
    const float* lp = log_probs + (size_t)n * CC;   // row t=0 of this sequence
    const float* p  = lp + myc;                     // my cell's emission column

    // ---- prologue ----
    if (tid < 2) { shA[0][tid] = NEGV; shA[1][tid] = NEGV; }  // front pad

    // alpha(t=0): cells 0 and 1 reachable
    shA[0][s + 2] = (s == 1) ? __ldg(p) * LOG2E : NEGV;
    float ecb = 0.f;
    if (tid == 0) {
        shA[0][2] = __ldg(lp) * LOG2E;              // cell 0 = blank
        ecb = __ldg(lp + tstride) * LOG2E;          // blank emission for t=1
    }
    float ec = __ldg(p + tstride) * LOG2E;          // my emission for t=1
    __syncthreads();

    // ---- main DP ----
    float* Acur = shA[0];
    float* Anew = shA[1];
    for (int t = 1; t < len; ++t) {
        // prefetch emissions for t+1 (latency hidden under this step's compute)
        const bool more = (t + 1 < len);
        float en = 0.f, enb = 0.f;
        if (more) {
            const size_t off = (size_t)(t + 1) * tstride;
            en = __ldg(p + off);
            if (tid == 0) enb = __ldg(lp + off);
        }

        // 3-way LSE with only 3 MUFU ops: sort inputs, max term is exp(0)=1
        float a0 = Acur[s + 2];
        float a1 = Acur[s + 1];
        float a2 = skip ? Acur[s] : NEGV;
        float hi01 = fmaxf(a0, a1), lo01 = fminf(a0, a1);
        float m   = fmaxf(hi01, a2);
        float mid = fmaxf(lo01, fminf(hi01, a2));
        float lo  = fminf(lo01, a2);
        float sum = 1.0f + ex2f(mid - m) + ex2f(lo - m);
        float nv  = m + lg2f(sum) + ec;

        Anew[s + 2] = nv;
        if (tid == 0) {                    // cell 0: blank self-loop, plain add
            Anew[2] = Acur[2] + ecb;
            ecb = enb * LOG2E;
        }
        ec = en * LOG2E;

        __syncthreads();
        float* tmp = Acur; Acur = Anew; Anew = tmp;
    }

    // ---- epilogue: combine last blank (2*tl) and last label (2*tl-1) ----
    if (tid == 0) {
        const int tl = target_lengths[n];
        const int i1 = 2 * tl + 2;        // +2 pad offset
        float v1 = Acur[i1];
        float v2 = Acur[i1 - 1];
        float m  = fmaxf(v1, v2);
        float loss = -(m + lg2f(ex2f(v1 - m) + ex2f(v2 - m))) * LN2;
        if (!isfinite(loss) || loss >= 1e10f) loss = 0.0f;
        out[n] = loss;
    }
}

extern "C" void kernel_launch(void* const* d_in, const int* in_sizes, int n_in,
                              void* d_out, int out_size)
{
    const float* log_probs      = (const float*)d_in[0];
    const int*   targets        = (const int*)  d_in[1];
    const int*   input_lengths  = (const int*)  d_in[2];
    const int*   target_lengths = (const int*)  d_in[3];
    float*       out            = (float*)d_out;

    const int N = in_sizes[2];   // batch from input_lengths element count

    ctc_loss_kernel<<<N, NTHREADS>>>(log_probs, targets, input_lengths,
                                     target_lengths, out, N);
}

// round 6
// speedup vs baseline: 1.1211x; 1.1211x over previous
#include <cuda_runtime.h>
#include <cuda_bf16.h>
#include <math.h>

// Problem shape (fixed by dataset): T=512, N=512, C=80, S=128, L=257
#define CC 80
#define SS 128
#define NEGV  (-1e30f)
#define LOG2E 1.4426950408889634f
#define LN2   0.6931471805599453f
#define WPB   4                  // warps per block = sequences per block

__device__ __forceinline__ float ex2f(float x) {
    float r; asm("ex2.approx.ftz.f32 %0, %1;" : "=f"(r) : "f"(x)); return r;
}
__device__ __forceinline__ float lg2f(float x) {
    float r; asm("lg2.approx.f32 %0, %1;" : "=f"(r) : "f"(x)); return r;
}
// 3-term log2-sum-exp2, largest term factored out (2 ex2 + 1 lg2)
__device__ __forceinline__ float lse3(float x, float y, float z) {
    float hi  = fmaxf(x, y), lo1 = fminf(x, y);
    float m   = fmaxf(hi, z);
    float mid = fmaxf(lo1, fminf(hi, z));
    float lo  = fminf(lo1, z);
    return m + lg2f(1.0f + ex2f(mid - m) + ex2f(lo - m));
}
// 2-term (1 ex2 + 1 lg2)
__device__ __forceinline__ float lse2(float x, float y) {
    float m = fmaxf(x, y), lo = fminf(x, y);
    return m + lg2f(1.0f + ex2f(lo - m));
}

// One WARP per sequence. Whole lattice (257 cells) lives in registers:
// lane l holds cells 8l+1 .. 8l+8 (a0..a7); cell 0 is a scalar on every lane
// (only lane 0's copy matters). No __syncthreads in the DP loop — the only
// cross-lane traffic is two shuffles per timestep.
__global__ __launch_bounds__(32 * WPB)
void ctc_loss_kernel(const float* __restrict__ log_probs,     // (T, N, C)
                     const int*   __restrict__ targets,       // (N, S)
                     const int*   __restrict__ input_lengths, // (N,)
                     const int*   __restrict__ target_lengths,// (N,)
                     float*       __restrict__ out,           // (N,)
                     int N)
{
    __shared__ float sh[WPB][260];           // epilogue scatter only

    const int lane = threadIdx.x & 31;
    const int w    = threadIdx.x >> 5;
    const int n    = blockIdx.x * WPB + w;
    if (n >= N) return;                       // no block-wide syncs used

    const int len = input_lengths[n];
    const size_t tstride = (size_t)N * CC;
    const float* lp = log_probs + (size_t)n * CC;

    // Labels of my 4 odd cells (8l+1,8l+3,8l+5,8l+7): targets[n][4l .. 4l+3]
    int4 tg = *reinterpret_cast<const int4*>(targets + n * SS + 4 * lane);
    const int c0 = tg.x, c1 = tg.y, c2 = tg.z, c3 = tg.w;
    const int prevT = __shfl_up_sync(0xffffffffu, c3, 1);   // targets[4l-1]
    const bool s0 = (lane > 0) && (c0 != prevT);
    const bool s1 = (c1 != c0);
    const bool s2 = (c2 != c1);
    const bool s3 = (c3 != c2);

    // ---- t = 0 init (log2 domain) ----
    float alpha0 = __ldg(lp) * LOG2E;                         // cell 0 (blank)
    float a0 = (lane == 0) ? __ldg(lp + c0) * LOG2E : NEGV;   // cell 1
    float a1 = NEGV, a2 = NEGV, a3 = NEGV, a4 = NEGV, a5 = NEGV, a6 = NEGV, a7 = NEGV;

    // emissions for t = 1 (T=512 so row 1 always exists)
    const float* r1 = lp + tstride;
    float ecb = __ldg(r1)      * LOG2E;
    float ec0 = __ldg(r1 + c0) * LOG2E;
    float ec1 = __ldg(r1 + c1) * LOG2E;
    float ec2 = __ldg(r1 + c2) * LOG2E;
    float ec3 = __ldg(r1 + c3) * LOG2E;

    // ---- DP loop: no barriers, two shuffles/step, 8-wide ILP per lane ----
    for (int t = 1; t < len; ++t) {
        // prefetch emissions for t+1 (clamped on the last iter; result unused)
        const int tn = (t + 1 < len) ? t + 1 : t;
        const float* row = lp + (size_t)tn * tstride;
        float pb = __ldg(row);
        float p0 = __ldg(row + c0);
        float p1 = __ldg(row + c1);
        float p2 = __ldg(row + c2);
        float p3 = __ldg(row + c3);

        // neighbor cells 8l and 8l-1 from lane l-1
        float left2 = __shfl_up_sync(0xffffffffu, a7, 1);     // cell 8l
        float left1 = __shfl_up_sync(0xffffffffu, a6, 1);     // cell 8l-1
        if (lane == 0) { left2 = alpha0; left1 = NEGV; }

        float n0 = lse3(a0, left2, s0 ? left1 : NEGV) + ec0;  // cell 8l+1 (label)
        float n1 = lse2(a1, a0) + ecb;                        // cell 8l+2 (blank)
        float n2 = lse3(a2, a1, s1 ? a0 : NEGV) + ec1;        // cell 8l+3
        float n3 = lse2(a3, a2) + ecb;                        // cell 8l+4
        float n4 = lse3(a4, a3, s2 ? a2 : NEGV) + ec2;        // cell 8l+5
        float n5 = lse2(a5, a4) + ecb;                        // cell 8l+6
        float n6 = lse3(a6, a5, s3 ? a4 : NEGV) + ec3;        // cell 8l+7
        float n7 = lse2(a7, a6) + ecb;                        // cell 8l+8
        alpha0 += ecb;                                        // cell 0 self-loop

        a0 = n0; a1 = n1; a2 = n2; a3 = n3; a4 = n4; a5 = n5; a6 = n6; a7 = n7;
        ecb = pb * LOG2E; ec0 = p0 * LOG2E; ec1 = p1 * LOG2E;
        ec2 = p2 * LOG2E; ec3 = p3 * LOG2E;
    }

    // ---- epilogue: dump lattice to smem, lane 0 combines final two cells ----
    float* S = sh[w];
    S[8 * lane + 1] = a0; S[8 * lane + 2] = a1;
    S[8 * lane + 3] = a2; S[8 * lane + 4] = a3;
    S[8 * lane + 5] = a4; S[8 * lane + 6] = a5;
    S[8 * lane + 7] = a6; S[8 * lane + 8] = a7;
    if (lane == 0) S[0] = alpha0;
    __syncwarp();

    if (lane == 0) {
        const int tl = target_lengths[n];
        float v1 = S[2 * tl];
        float v2 = S[2 * tl - 1];
        float m  = fmaxf(v1, v2);
        float loss = -(m + lg2f(ex2f(v1 - m) + ex2f(v2 - m))) * LN2;
        if (!isfinite(loss) || loss >= 1e10f) loss = 0.0f;
        out[n] = loss;
    }
}

extern "C" void kernel_launch(void* const* d_in, const int* in_sizes, int n_in,
                              void* d_out, int out_size)
{
    const float* log_probs      = (const float*)d_in[0];
    const int*   targets        = (const int*)  d_in[1];
    const int*   input_lengths  = (const int*)  d_in[2];
    const int*   target_lengths = (const int*)  d_in[3];
    float*       out            = (float*)d_out;

    const int N = in_sizes[2];
    const int blocks = (N + WPB - 1) / WPB;

    ctc_loss_kernel<<<blocks, 32 * WPB>>>(log_probs, targets, input_lengths,
                                          target_lengths, out, N);
}

// round 7
// speedup vs baseline: 3.0742x; 2.7421x over previous
#include <cuda_runtime.h>
#include <cuda_bf16.h>
#include <math.h>

// Problem shape (fixed by dataset): T=512, N=512, C=80, S=128, L=257
#define CC 80
#define SS 128
#define NEGV  (-1e30f)
#define LOG2E 1.4426950408889634f
#define LN2   0.6931471805599453f
#define NT    128                // 4 warps; thread tid owns cells 2tid+1, 2tid+2

__device__ __forceinline__ float ex2f(float x) {
    float r; asm("ex2.approx.ftz.f32 %0, %1;" : "=f"(r) : "f"(x)); return r;
}
__device__ __forceinline__ float lg2f(float x) {
    float r; asm("lg2.approx.f32 %0, %1;" : "=f"(r) : "f"(x)); return r;
}
// 3-term log2-sum-exp2 with input sort: 2 ex2 + 1 lg2 (min MUFU pressure)
__device__ __forceinline__ float lse3(float x, float y, float z) {
    float hi  = fmaxf(x, y), lo1 = fminf(x, y);
    float m   = fmaxf(hi, z);
    float mid = fmaxf(lo1, fminf(hi, z));
    float lo  = fminf(lo1, z);
    return m + lg2f(1.0f + ex2f(mid - m) + ex2f(lo - m));
}
// 2-term: 1 ex2 + 1 lg2
__device__ __forceinline__ float lse2(float x, float y) {
    float m = fmaxf(x, y), lo = fminf(x, y);
    return m + lg2f(1.0f + ex2f(lo - m));
}

// One block (128 threads, 4 warps) per sequence. Whole lattice in registers:
// a0 = cell 2tid+1 (label cell), a1 = cell 2tid+2 (blank cell); cell 0 is the
// scalar alpha0 (tid 0's copy authoritative). Left neighbors via shfl_up;
// warp boundaries via a parity-double-buffered 2-float smem slot.
__global__ __launch_bounds__(NT)
void ctc_loss_kernel(const float* __restrict__ log_probs,     // (T, N, C)
                     const int*   __restrict__ targets,       // (N, S)
                     const int*   __restrict__ input_lengths, // (N,)
                     const int*   __restrict__ target_lengths,// (N,)
                     float*       __restrict__ out,           // (N,)
                     int N)
{
    __shared__ float bnd[2][4][2];   // [step parity][warp][{a0,a1}] of lane 31
    __shared__ float fin[260];       // epilogue gather

    const int tid  = threadIdx.x;
    const int lane = tid & 31;
    const int w    = tid >> 5;
    const int n    = blockIdx.x;
    const int len  = input_lengths[n];

    // Time-invariant: my label (cell 2tid+1) and skip permission
    const int  c    = targets[n * SS + tid];
    const bool skip = (tid > 0) && (c != targets[n * SS + tid - 1]);

    const size_t tstride = (size_t)N * CC;
    const float* lp = log_probs + (size_t)n * CC;

    // ---- t = 0 (log2 domain) ----
    float alpha0 = __ldg(lp) * LOG2E;                       // cell 0 (blank)
    float a0 = (tid == 0) ? __ldg(lp + c) * LOG2E : NEGV;   // cell 1
    float a1 = NEGV;                                        // cell 2

    if (lane == 31) { bnd[0][w][0] = a0; bnd[0][w][1] = a1; }

    // raw emissions for t = 1 (row 1 always exists: T=512)
    const float* r1 = lp + tstride;
    float pc = __ldg(r1 + c);     // my label emission
    float pb = __ldg(r1);         // blank emission (uniform -> broadcast)
    __syncthreads();

    // ---- DP loop: 1 bar/step, 2 shuffles, reg-prefetched emissions ----
    for (int t = 1; t < len; ++t) {
        // prefetch raw emissions for t+1 (clamped to last valid row)
        const int tn = (t + 1 < len) ? t + 1 : t;
        const float* row = lp + (size_t)tn * tstride;
        float qc = __ldg(row + c);
        float qb = __ldg(row);

        // left neighbors: cells 2tid and 2tid-1
        float l1 = __shfl_up_sync(0xffffffffu, a1, 1);
        float l0 = __shfl_up_sync(0xffffffffu, a0, 1);
        if (lane == 0) {
            if (w == 0) { l1 = alpha0; l0 = NEGV; }
            else        { l1 = bnd[(t - 1) & 1][w - 1][1];
                          l0 = bnd[(t - 1) & 1][w - 1][0]; }
        }

        float n0 = fmaf(pc, LOG2E, lse3(a0, l1, skip ? l0 : NEGV)); // cell 2tid+1
        float n1 = fmaf(pb, LOG2E, lse2(a1, a0));                   // cell 2tid+2
        alpha0   = fmaf(pb, LOG2E, alpha0);                         // cell 0

        a0 = n0; a1 = n1;
        if (lane == 31) { bnd[t & 1][w][0] = a0; bnd[t & 1][w][1] = a1; }
        pc = qc; pb = qb;
        __syncthreads();
    }

    // ---- epilogue: gather lattice, tid 0 combines cells 2*tl and 2*tl-1 ----
    fin[2 * tid + 1] = a0;
    fin[2 * tid + 2] = a1;
    if (tid == 0) fin[0] = alpha0;
    __syncthreads();

    if (tid == 0) {
        const int tl = target_lengths[n];
        float v1 = fin[2 * tl];
        float v2 = fin[2 * tl - 1];
        float m  = fmaxf(v1, v2);
        float loss = -(m + lg2f(ex2f(v1 - m) + ex2f(v2 - m))) * LN2;
        if (!isfinite(loss) || loss >= 1e10f) loss = 0.0f;
        out[n] = loss;
    }
}

extern "C" void kernel_launch(void* const* d_in, const int* in_sizes, int n_in,
                              void* d_out, int out_size)
{
    const float* log_probs      = (const float*)d_in[0];
    const int*   targets        = (const int*)  d_in[1];
    const int*   input_lengths  = (const int*)  d_in[2];
    const int*   target_lengths = (const int*)  d_in[3];
    float*       out            = (float*)d_out;

    const int N = in_sizes[2];   // batch from input_lengths element count

    ctc_loss_kernel<<<N, NT>>>(log_probs, targets, input_lengths,
                               target_lengths, out, N);
}